// round 1
// baseline (speedup 1.0000x reference)
#include <cuda_runtime.h>
#include <math.h>

// Problem constants
#define BB 16
#define CF 96
#define HH 128
#define WW 128
#define HW (HH*WW)

// Scratch (static device allocations are allowed)
__device__ float g_flow[BB*2*HW];        //   2 MB
__device__ float g_feat2[BB*CF*HW];      //  96 MB
__device__ float g_corr[BB*49*HW];       //  49 MB
__device__ float g_x1[BB*128*HW];        // 128 MB
__device__ float g_x2[BB*64*HW];         //  64 MB
__device__ float g_x3[BB*32*HW];         //  32 MB

// ---------------------------------------------------------------------------
// 1) upflow: transposed conv, stride 2, 4x4 kernel, groups=2
//    out[b,c,oy,ox] = sum_{ky,kx : oy+ky even, ox+kx even}
//                     flow[b,c,(oy+ky-2)/2,(ox+kx-2)/2] * wu[c,0,3-ky,3-kx]
// ---------------------------------------------------------------------------
__global__ void k_upflow(const float* __restrict__ flow, const float* __restrict__ wu)
{
    int idx = blockIdx.x * blockDim.x + threadIdx.x;
    if (idx >= BB*2*HW) return;
    int ox = idx & 127;
    int oy = (idx >> 7) & 127;
    int c  = (idx >> 14) & 1;
    int b  = idx >> 15;
    const float* f  = flow + (b*2 + c) * 64 * 64;
    const float* wc = wu + c * 16;
    int py = oy & 1, px = ox & 1;
    float s = 0.f;
#pragma unroll
    for (int i = 0; i < 2; i++) {
        int ky  = py + 2*i;
        int jy2 = oy + ky - 2;
        if (jy2 < 0 || jy2 > 126) continue;
        int jy = jy2 >> 1;
#pragma unroll
        for (int j = 0; j < 2; j++) {
            int kx  = px + 2*j;
            int jx2 = ox + kx - 2;
            if (jx2 < 0 || jx2 > 126) continue;
            int jx = jx2 >> 1;
            s += f[jy*64 + jx] * wc[(3-ky)*4 + (3-kx)];
        }
    }
    g_flow[idx] = s;
}

// ---------------------------------------------------------------------------
// 2) backward warp of featSecond by 2.5*flow, bilinear zero-border + mask
// ---------------------------------------------------------------------------
__global__ void k_warp(const float* __restrict__ feat)
{
    int idx = blockIdx.x * blockDim.x + threadIdx.x;
    if (idx >= BB*HW) return;
    int x = idx & 127;
    int y = (idx >> 7) & 127;
    int b = idx >> 14;

    float fx = (float)x + 2.5f * g_flow[(b*2 + 0)*HW + y*WW + x];
    float fy = (float)y + 2.5f * g_flow[(b*2 + 1)*HW + y*WW + x];

    float x0f = floorf(fx), y0f = floorf(fy);
    float x1f = x0f + 1.f,  y1f = y0f + 1.f;
    float wa = (x1f - fx) * (y1f - fy);
    float wb = (fx - x0f) * (y1f - fy);
    float wc = (x1f - fx) * (fy - y0f);
    float wd = (fx - x0f) * (fy - y0f);

    int x0 = (int)x0f, y0 = (int)y0f, x1 = x0 + 1, y1 = y0 + 1;
    float vx0 = (x0 >= 0 && x0 < WW) ? 1.f : 0.f;
    float vx1 = (x1 >= 0 && x1 < WW) ? 1.f : 0.f;
    float vy0 = (y0 >= 0 && y0 < HH) ? 1.f : 0.f;
    float vy1 = (y1 >= 0 && y1 < HH) ? 1.f : 0.f;
    float va = vx0*vy0, vb = vx1*vy0, vc = vx0*vy1, vd = vx1*vy1;

    float onew = wa*va + wb*vb + wc*vc + wd*vd;
    float mask = (onew > 0.999f) ? 1.f : 0.f;

    float ka = wa*va*mask, kb = wb*vb*mask, kc = wc*vc*mask, kd = wd*vd*mask;

    int cx0 = min(max(x0, 0), WW-1), cx1 = min(max(x1, 0), WW-1);
    int cy0 = min(max(y0, 0), HH-1), cy1 = min(max(y1, 0), HH-1);
    int ia = cy0*WW + cx0, ib2 = cy0*WW + cx1, ic2 = cy1*WW + cx0, id2 = cy1*WW + cx1;

    const float* base = feat + (size_t)b*CF*HW;
    float* out = g_feat2 + (size_t)b*CF*HW + y*WW + x;
#pragma unroll 4
    for (int c = 0; c < CF; c++) {
        const float* p = base + c*HW;
        out[c*HW] = ka*__ldg(p+ia) + kb*__ldg(p+ib2) + kc*__ldg(p+ic2) + kd*__ldg(p+id2);
    }
}

// ---------------------------------------------------------------------------
// 3) correlation (7x7 displacements, mean over 96 channels) + leaky relu
//    block (16,16), grid (8,8,B). smem tile of feat2 with 3-halo (22x22).
// ---------------------------------------------------------------------------
__global__ __launch_bounds__(256) void k_corr(const float* __restrict__ f1)
{
    __shared__ float s2[22*22];
    int tx = threadIdx.x, ty = threadIdx.y;
    int tid = ty*16 + tx;
    int bx0 = blockIdx.x * 16, by0 = blockIdx.y * 16;
    int b = blockIdx.z;
    int x = bx0 + tx, y = by0 + ty;
    int ox0 = bx0 - 3, oy0 = by0 - 3;

    float acc[49];
#pragma unroll
    for (int d = 0; d < 49; d++) acc[d] = 0.f;

    const float* F1 = f1 + (size_t)b*CF*HW;
    const float* F2 = g_feat2 + (size_t)b*CF*HW;

    for (int c = 0; c < CF; c++) {
        __syncthreads();
#pragma unroll
        for (int i = tid; i < 22*22; i += 256) {
            int ly = i / 22, lx = i - ly*22;
            int gy = oy0 + ly, gx = ox0 + lx;
            float v = 0.f;
            if (gy >= 0 && gy < HH && gx >= 0 && gx < WW)
                v = F2[c*HW + gy*WW + gx];
            s2[i] = v;
        }
        float a1 = F1[c*HW + y*WW + x];
        __syncthreads();
#pragma unroll
        for (int dy = 0; dy < 7; dy++)
#pragma unroll
            for (int dx = 0; dx < 7; dx++)
                acc[dy*7 + dx] += a1 * s2[(ty+dy)*22 + tx + dx];
    }

    const float inv = 1.f / 96.f;
    float* out = g_corr + (size_t)b*49*HW + y*WW + x;
#pragma unroll
    for (int d = 0; d < 49; d++) {
        float v = acc[d] * inv;
        out[d*HW] = (v >= 0.f) ? v : 0.1f * v;
    }
}

// ---------------------------------------------------------------------------
// 4) generic 3x3 conv, pad 1, NCHW, OCT output channels per block + lrelu
// ---------------------------------------------------------------------------
template <int IC, int OC, int OCT, bool RELU>
__global__ __launch_bounds__(256) void k_conv3(const float* __restrict__ in,
                                               const float* __restrict__ w,
                                               const float* __restrict__ bias,
                                               float* __restrict__ out)
{
    __shared__ float s_in[18*18];
    __shared__ float s_w[OCT*9];
    int tx = threadIdx.x, ty = threadIdx.y;
    int tid = ty*16 + tx;
    int tile = blockIdx.x;
    int tbx = (tile & 7) * 16, tby = (tile >> 3) * 16;
    int ocb = blockIdx.y * OCT;
    int b = blockIdx.z;
    int x = tbx + tx, y = tby + ty;

    float acc[OCT];
#pragma unroll
    for (int o = 0; o < OCT; o++) acc[o] = bias[ocb + o];

    const float* IN = in + (size_t)b*IC*HW;

    for (int ic = 0; ic < IC; ic++) {
        __syncthreads();
        // stage 18x18 input tile (1-halo, zero pad)
#pragma unroll
        for (int i = tid; i < 324; i += 256) {
            int ly = i / 18, lx = i - ly*18;
            int gy = tby - 1 + ly, gx = tbx - 1 + lx;
            float v = 0.f;
            if (gy >= 0 && gy < HH && gx >= 0 && gx < WW)
                v = IN[ic*HW + gy*WW + gx];
            s_in[i] = v;
        }
        if (tid < OCT*9) {
            int o = tid / 9, t = tid - o*9;
            s_w[tid] = w[((size_t)(ocb + o)*IC + ic)*9 + t];
        }
        __syncthreads();

        float iv[9];
#pragma unroll
        for (int r = 0; r < 3; r++)
#pragma unroll
            for (int s = 0; s < 3; s++)
                iv[r*3 + s] = s_in[(ty + r)*18 + tx + s];
#pragma unroll
        for (int o = 0; o < OCT; o++) {
            float a = acc[o];
#pragma unroll
            for (int t = 0; t < 9; t++)
                a += iv[t] * s_w[o*9 + t];
            acc[o] = a;
        }
    }

    float* O = out + ((size_t)b*OC + ocb)*HW + y*WW + x;
#pragma unroll
    for (int o = 0; o < OCT; o++) {
        float v = acc[o];
        if (RELU) v = (v >= 0.f) ? v : 0.1f * v;
        O[o*HW] = v;
    }
}

// ---------------------------------------------------------------------------
// 5) final 5x5 conv (32 -> 2, pad 2), add upsampled flow, write d_out
// ---------------------------------------------------------------------------
__global__ __launch_bounds__(256) void k_conv5(const float* __restrict__ w,
                                               const float* __restrict__ bias,
                                               float* __restrict__ out)
{
    __shared__ float s_in[20*20];
    __shared__ float s_w[2*25];
    int tx = threadIdx.x, ty = threadIdx.y;
    int tid = ty*16 + tx;
    int tile = blockIdx.x;
    int tbx = (tile & 7) * 16, tby = (tile >> 3) * 16;
    int b = blockIdx.z;
    int x = tbx + tx, y = tby + ty;

    float acc0 = bias[0], acc1 = bias[1];
    const float* IN = g_x3 + (size_t)b*32*HW;

    for (int ic = 0; ic < 32; ic++) {
        __syncthreads();
#pragma unroll
        for (int i = tid; i < 400; i += 256) {
            int ly = i / 20, lx = i - ly*20;
            int gy = tby - 2 + ly, gx = tbx - 2 + lx;
            float v = 0.f;
            if (gy >= 0 && gy < HH && gx >= 0 && gx < WW)
                v = IN[ic*HW + gy*WW + gx];
            s_in[i] = v;
        }
        if (tid < 50) {
            int o = tid / 25, t = tid - o*25;
            s_w[tid] = w[((size_t)o*32 + ic)*25 + t];
        }
        __syncthreads();

#pragma unroll
        for (int t = 0; t < 25; t++) {
            int r = t / 5, s = t - r*5;
            float iv = s_in[(ty + r)*20 + tx + s];
            acc0 += iv * s_w[t];
            acc1 += iv * s_w[25 + t];
        }
    }

    int pix = y*WW + x;
    out[((size_t)b*2 + 0)*HW + pix] = g_flow[(b*2 + 0)*HW + pix] + acc0;
    out[((size_t)b*2 + 1)*HW + pix] = g_flow[(b*2 + 1)*HW + pix] + acc1;
}

// ---------------------------------------------------------------------------
extern "C" void kernel_launch(void* const* d_in, const int* in_sizes, int n_in,
                              void* d_out, int out_size)
{
    // metadata order: tensorFirst, tensorSecond, featFirst, featSecond,
    //                 tensorFlow, wu, w1, b1, w2, b2, w3, b3, w4, b4
    const float* featFirst  = (const float*)d_in[2];
    const float* featSecond = (const float*)d_in[3];
    const float* tflow      = (const float*)d_in[4];
    const float* wu         = (const float*)d_in[5];
    const float* w1 = (const float*)d_in[6];
    const float* b1 = (const float*)d_in[7];
    const float* w2 = (const float*)d_in[8];
    const float* b2 = (const float*)d_in[9];
    const float* w3 = (const float*)d_in[10];
    const float* b3 = (const float*)d_in[11];
    const float* w4 = (const float*)d_in[12];
    const float* b4 = (const float*)d_in[13];

    float *corrp, *x1p, *x2p, *x3p;
    cudaGetSymbolAddress((void**)&corrp, g_corr);
    cudaGetSymbolAddress((void**)&x1p, g_x1);
    cudaGetSymbolAddress((void**)&x2p, g_x2);
    cudaGetSymbolAddress((void**)&x3p, g_x3);

    dim3 blk(16, 16);

    k_upflow<<<(BB*2*HW + 255)/256, 256>>>(tflow, wu);
    k_warp<<<(BB*HW + 255)/256, 256>>>(featSecond);
    k_corr<<<dim3(8, 8, BB), blk>>>(featFirst);
    k_conv3<49, 128, 8, true><<<dim3(64, 16, BB), blk>>>(corrp, w1, b1, x1p);
    k_conv3<128, 64, 8, true><<<dim3(64,  8, BB), blk>>>(x1p,  w2, b2, x2p);
    k_conv3<64,  32, 8, true><<<dim3(64,  4, BB), blk>>>(x2p,  w3, b3, x3p);
    k_conv5<<<dim3(64, 1, BB), blk>>>(w4, b4, (float*)d_out);
}